// round 8
// baseline (speedup 1.0000x reference)
#include <cuda_runtime.h>
#include <cuda_fp16.h>
#include <cstdint>

// Problem constants (fixed by the dataset)
#define VOCAB  10000
#define DD     512
#define NL     4
#define BB     32
#define SS     1024
#define M_TOT  (BB * SS)     // 32768
#define N_TOT  (3 * DD)      // 1536
#define K_TOT  DD            // 512

// ---------------------------------------------------------------------------
// Scratch (device globals — allocation-free per harness rules)
// ---------------------------------------------------------------------------
__device__ float         g_U[(size_t)M_TOT * N_TOT];          // 201 MB, one layer's U
__device__ __half        g_x16[2][(size_t)M_TOT * DD];        // fp16 x, ping-pong
__device__ __half        g_W16[(size_t)NL * N_TOT * K_TOT];   // W^T fp16  [l][n][k]
__device__ unsigned int  g_padbits[BB][SS / 32];              // bit s%32 of word s/32: pad at (b,s)

// ---------------------------------------------------------------------------
// PTX helpers (sm_80-level; compiles for plain sm_100)
// ---------------------------------------------------------------------------
__device__ __forceinline__ uint32_t smem_u32(const void* p) {
    uint32_t a;
    asm("{ .reg .u64 t; cvta.to.shared.u64 t, %1; cvt.u32.u64 %0, t; }" : "=r"(a) : "l"(p));
    return a;
}
__device__ __forceinline__ void cpa16(uint32_t dst, const void* src) {
    asm volatile("cp.async.cg.shared.global [%0], [%1], 16;" :: "r"(dst), "l"(src));
}
__device__ __forceinline__ void cpa4(uint32_t dst, const void* src) {
    asm volatile("cp.async.ca.shared.global [%0], [%1], 4;" :: "r"(dst), "l"(src));
}
__device__ __forceinline__ void cp_commit() {
    asm volatile("cp.async.commit_group;" ::: "memory");
}
template <int N> __device__ __forceinline__ void cp_wait() {
    asm volatile("cp.async.wait_group %0;" :: "n"(N) : "memory");
}
__device__ __forceinline__ float4 lds128f(uint32_t a) {
    float4 v;
    asm volatile("ld.shared.v4.f32 {%0,%1,%2,%3}, [%4];"
                 : "=f"(v.x), "=f"(v.y), "=f"(v.z), "=f"(v.w) : "r"(a));
    return v;
}
__device__ __forceinline__ void ldm4(uint32_t* r, uint32_t addr) {
    asm volatile("ldmatrix.sync.aligned.m8n8.x4.shared.b16 {%0,%1,%2,%3}, [%4];"
                 : "=r"(r[0]), "=r"(r[1]), "=r"(r[2]), "=r"(r[3]) : "r"(addr));
}
__device__ __forceinline__ void mma16816(float* d, const uint32_t* a, const uint32_t* b) {
    asm volatile("mma.sync.aligned.m16n8k16.row.col.f32.f16.f16.f32 "
                 "{%0,%1,%2,%3}, {%4,%5,%6,%7}, {%8,%9}, {%0,%1,%2,%3};"
                 : "+f"(d[0]), "+f"(d[1]), "+f"(d[2]), "+f"(d[3])
                 : "r"(a[0]), "r"(a[1]), "r"(a[2]), "r"(a[3]), "r"(b[0]), "r"(b[1]));
}

// ---------------------------------------------------------------------------
// GEMM: U[m][n] = sum_k x16[m][k] * W16[n][k]   (fp16 in, fp32 accumulate)
// CTA tile 128x128, BK=64 (128-B swizzled rows), 3-stage cp.async pipeline,
// one __syncthreads per chunk; fully unrolled chunk loop (constant stages).
// ---------------------------------------------------------------------------
#define BM 128
#define BN 128
#define BK 64
#define AS_BYTES    (BM * BK * 2)               // 16384
#define BS_BYTES    (BN * BK * 2)               // 16384
#define STAGE_BYTES (AS_BYTES + BS_BYTES)       // 32768
#define GEMM_SMEM   (3 * STAGE_BYTES)           // 98304

__global__ __launch_bounds__(256, 2) void sru_gemm_kernel(int layer, int xin) {
    extern __shared__ char sm[];
    const uint32_t sb = smem_u32(sm);
    const int tid = threadIdx.x, lane = tid & 31, wid = tid >> 5;
    const int n0 = blockIdx.x * BN;     // n fastest -> 12 CTAs share the A tile (L2-hot)
    const int m0 = blockIdx.y * BM;

    const __half* __restrict__ A  = g_x16[xin] + (size_t)m0 * K_TOT;
    const __half* __restrict__ Bm = g_W16 + (size_t)layer * N_TOT * K_TOT + (size_t)n0 * K_TOT;

    auto load_chunk = [&](int stage, int kc) {
        const uint32_t ab = sb + stage * STAGE_BYTES;
        const uint32_t bb = ab + AS_BYTES;
#pragma unroll
        for (int i = 0; i < 4; ++i) {
            const int j = tid + i * 256;             // 0..1023 : (row, 16B-seg)
            const int r = j >> 3, seg = j & 7;
            const uint32_t soff = (uint32_t)(r * 128 + ((seg * 16) ^ ((r & 7) * 16)));
            const size_t go = (size_t)r * K_TOT + kc * 64 + seg * 8;
            cpa16(ab + soff, A + go);
            cpa16(bb + soff, Bm + go);
        }
        cp_commit();
    };

    const int wm = wid >> 2, wn = wid & 3;           // warp tile: rows wm*64, cols wn*32
    const int grp = lane >> 3, l8 = lane & 7;
    const int a_r  = ((grp & 1) << 3) + l8;
    const int a_kh = grp >> 1;
    const int b_r  = ((grp >> 1) << 3) + l8;
    const int b_kh = grp & 1;

    uint32_t swa[4], swb[4];
#pragma unroll
    for (int ks = 0; ks < 4; ++ks) {
        swa[ks] = (uint32_t)((ks * 32 + a_kh * 16) ^ ((a_r & 7) * 16));
        swb[ks] = (uint32_t)((ks * 32 + b_kh * 16) ^ ((b_r & 7) * 16));
    }
    const uint32_t a_row_base = (uint32_t)((wm * 64 + a_r) * 128);
    const uint32_t b_row_base = (uint32_t)((wn * 32 + b_r) * 128);

    float acc[4][4][4];
#pragma unroll
    for (int mi = 0; mi < 4; ++mi)
#pragma unroll
        for (int ni = 0; ni < 4; ++ni)
#pragma unroll
            for (int q = 0; q < 4; ++q) acc[mi][ni][q] = 0.0f;

    load_chunk(0, 0);
    load_chunk(1, 1);

#pragma unroll
    for (int c = 0; c < 8; ++c) {
        if (c < 7) cp_wait<1>(); else cp_wait<0>();
        __syncthreads();
        // Issue next-chunk loads FIRST: target stage (c+2)%3 == (c-1)%3 whose
        // readers (iter c-1 compute) all passed the barrier above.
        if (c + 2 < 8) load_chunk((c + 2) % 3, c + 2);

        const uint32_t ab = sb + (c % 3) * STAGE_BYTES;
        const uint32_t bb = ab + AS_BYTES;
        const uint32_t abase = ab + a_row_base;
        const uint32_t bbase = bb + b_row_base;
#pragma unroll
        for (int ks = 0; ks < 4; ++ks) {
            uint32_t areg[4][4], breg[2][4];
#pragma unroll
            for (int nq = 0; nq < 2; ++nq) ldm4(breg[nq], bbase + nq * 2048 + swb[ks]);
#pragma unroll
            for (int mi = 0; mi < 4; ++mi) ldm4(areg[mi], abase + mi * 2048 + swa[ks]);
#pragma unroll
            for (int mi = 0; mi < 4; ++mi)
#pragma unroll
                for (int ni = 0; ni < 4; ++ni)
                    mma16816(acc[mi][ni], areg[mi], &breg[ni >> 1][(ni & 1) * 2]);
        }
    }

    const int er = lane >> 2, ec = (lane & 3) * 2;
    float* __restrict__ Uo = g_U + (size_t)m0 * N_TOT + n0;
#pragma unroll
    for (int mi = 0; mi < 4; ++mi) {
#pragma unroll
        for (int ni = 0; ni < 4; ++ni) {
            const int m = wm * 64 + mi * 16 + er;
            const int n = wn * 32 + ni * 8 + ec;
            float2 v0 = make_float2(acc[mi][ni][0], acc[mi][ni][1]);
            float2 v1 = make_float2(acc[mi][ni][2], acc[mi][ni][3]);
            *(float2*)&Uo[(size_t)m * N_TOT + n]       = v0;
            *(float2*)&Uo[(size_t)(m + 8) * N_TOT + n] = v1;
        }
    }
}

// ---------------------------------------------------------------------------
// SRU recurrence: one thread per (b, d) lane, serial over S.
// 128 blocks x 128 threads. U streams arrive via a 16-slot cp.async smem ring.
// RACE FIX vs R7: refill for slot (s0+SD) is issued AFTER do4(s0) consumes
// that slot (s0+SD aliases s0 mod SD). Consume-then-refill, same-thread order.
// ---------------------------------------------------------------------------
__device__ __forceinline__ float htanh(float z) {
    float r;
    asm("tanh.approx.f32 %0, %1;" : "=f"(r) : "f"(z));
    return r;
}
__device__ __forceinline__ float fast_sigmoid(float z) {
    return fmaf(0.5f, htanh(0.5f * z), 0.5f);    // sigma(z) = 0.5*tanh(z/2)+0.5
}

#define SD 16   // ring depth (steps)

__global__ __launch_bounds__(128) void sru_scan_kernel(int layer, int xin,
                                                       const float* __restrict__ vall,
                                                       const float* __restrict__ ball,
                                                       float* __restrict__ dout, int last) {
    __shared__ float4 ring[4][SD][32];              // [warp][slot][lane] : u0, uf, ur, (pad)
    const int tid = threadIdx.x;
    const int lane = tid & 31, w = tid >> 5;
    const int t = blockIdx.x * 128 + tid;           // 0..16383
    const int d = t & (DD - 1);
    const int b = t >> 9;

    const float* __restrict__ U = g_U;
    const unsigned short* __restrict__ x16 = (const unsigned short*)g_x16[xin];
    __half* __restrict__ o16 = g_x16[xin ^ 1];

    const uint32_t slot0 = smem_u32(&ring[w][0][lane]);

    const float vf = vall[layer * 1024 + d];
    const float vr = vall[layer * 1024 + 512 + d];
    const float bf = ball[layer * 1024 + d];
    const float br = ball[layer * 1024 + 512 + d];

    // Issue one commit group covering steps s..s+3 (12 B of U per step).
    auto issue4 = [&](int s) {
#pragma unroll
        for (int i = 0; i < 4; ++i) {
            const int row = (s + i) * BB + b;
            const float* up = U + (size_t)row * N_TOT + d;
            const uint32_t dst = slot0 + (uint32_t)(((s + i) & (SD - 1)) << 9);  // slot*512B
            cpa4(dst,     up);
            cpa4(dst + 4, up + 512);
            cpa4(dst + 8, up + 1024);
        }
        cp_commit();
    };

    unsigned short xr[SD];
    issue4(0); issue4(4); issue4(8); issue4(12);
#pragma unroll
    for (int i = 0; i < SD; ++i)
        xr[i] = __ldcs(x16 + (size_t)(i * BB + b) * DD + d);

    float c = 0.0f;

    auto do4 = [&](int s0) {
        const unsigned int pw = g_padbits[b][s0 >> 5] >> (s0 & 31);
#pragma unroll
        for (int k = 0; k < 4; ++k) {
            const int s = s0 + k;
            const float4 uu = lds128f(slot0 + (uint32_t)((s & (SD - 1)) << 9));
            __half_raw hxr; hxr.x = xr[s & (SD - 1)];
            const float x_ = __half2float((__half)hxr);
            if (s + SD < SS)
                xr[s & (SD - 1)] = __ldcs(x16 + (size_t)((s + SD) * BB + b) * DD + d);

            const int pd = (pw >> k) & 1;
            const float f = fast_sigmoid(fmaf(vf, c, uu.y + bf));
            const float r = fast_sigmoid(fmaf(vr, c, uu.z + br));
            float cn = fmaf(f, c - uu.x, uu.x);
            cn = pd ? c : cn;
            float h = fmaf(r, htanh(cn) - x_, x_);
            h = pd ? 0.0f : h;
            c = cn;

            const int row = s * BB + b;
            if (!last) o16[(size_t)row * DD + d] = __float2half_rn(h);
            else       dout[((size_t)b * SS + s) * DD + d] = h;
        }
    };

    // Steady state: wait oldest group, CONSUME its slots, then reuse them for
    // the refill (issue after do4 — the fix for the R7 WAR race).
    for (int s0 = 0; s0 < SS - 12; s0 += 4) {
        cp_wait<3>();
        do4(s0);
        if (s0 + SD < SS) issue4(s0 + SD);
    }
    cp_wait<2>(); do4(SS - 12);
    cp_wait<1>(); do4(SS - 8);
    cp_wait<0>(); do4(SS - 4);
}

// ---------------------------------------------------------------------------
// Prep kernels
// ---------------------------------------------------------------------------
__global__ void sru_embed_kernel(const int* __restrict__ ids, const float* __restrict__ emb) {
    const int idx = blockIdx.x * blockDim.x + threadIdx.x;   // (m, quad of 4)
    if (idx >= M_TOT * 128) return;
    const int m = idx >> 7, q = idx & 127;
    const int b = m & 31, s = m >> 5;                        // m = s*32 + b
    const int id = __ldg(ids + b * SS + s);
    const float4 e = *(const float4*)(emb + (size_t)id * DD + q * 4);

    union { __half v[4]; uint2 u; } hh;
    hh.v[0] = __float2half_rn(e.x);
    hh.v[1] = __float2half_rn(e.y);
    hh.v[2] = __float2half_rn(e.z);
    hh.v[3] = __float2half_rn(e.w);
    *(uint2*)(g_x16[0] + (size_t)m * DD + q * 4) = hh.u;
}

// W[l][k][n] -> g_W16[l][n][k], coalesced both ways via 32x33 smem tile
__global__ __launch_bounds__(1024) void sru_prepw_kernel(const float* __restrict__ W) {
    __shared__ float tile[32][33];
    const int k0 = blockIdx.x * 32;      // 16 tiles
    const int n0 = blockIdx.y * 32;      // 48 tiles
    const int l  = blockIdx.z;           // 4
    const int tx = threadIdx.x & 31, ty = threadIdx.x >> 5;
    tile[ty][tx] = __ldg(W + (size_t)l * K_TOT * N_TOT + (size_t)(k0 + ty) * N_TOT + n0 + tx);
    __syncthreads();
    g_W16[(size_t)l * N_TOT * K_TOT + (size_t)(n0 + ty) * K_TOT + k0 + tx] =
        __float2half_rn(tile[tx][ty]);
}

// Mask dtype auto-detect: int32 {0,1} / float32 {0,1.0f} / packed bytes.
// Produces the transposed pad bitmask g_padbits[b][s/32].
__global__ void sru_prepmask_kernel(const void* __restrict__ mraw) {
    __shared__ int f_not01, f_notf;
    const int tid = threadIdx.x;
    if (tid == 0) { f_not01 = 0; f_notf = 0; }
    __syncthreads();
    const unsigned int* w = (const unsigned int*)mraw;
    int a = 0, fl = 0;
    for (int i = tid; i < M_TOT / 4; i += 1024) {     // safe subset for all dtypes
        const unsigned int x = w[i];
        if (x > 1u) a = 1;
        if (x != 0u && x != 0x3F800000u) fl = 1;
    }
    if (a)  atomicExch(&f_not01, 1);
    if (fl) atomicExch(&f_notf, 1);
    __syncthreads();
    const int mode = (!f_not01) ? 0 : ((!f_notf) ? 1 : 2);
    const int b = tid >> 5, wrd = tid & 31;
    unsigned int bits = 0;
#pragma unroll 4
    for (int i = 0; i < 32; ++i) {
        const int s = wrd * 32 + i;
        const int j = b * SS + s;                      // mask is [B][S]
        int mv;
        if (mode == 0)      mv = ((const int*)mraw)[j] != 0;
        else if (mode == 1) mv = ((const unsigned int*)mraw)[j] != 0u;
        else                mv = ((const unsigned char*)mraw)[j] != 0;
        if (!mv) bits |= (1u << i);                    // pad bit
    }
    g_padbits[b][wrd] = bits;
}

// ---------------------------------------------------------------------------
// Launch
// ---------------------------------------------------------------------------
extern "C" void kernel_launch(void* const* d_in, const int* in_sizes, int n_in,
                              void* d_out, int out_size) {
    const int*   ids  = (const int*)d_in[0];
    const void*  mask = d_in[1];
    const float* emb  = (const float*)d_in[2];
    const float* W    = (const float*)d_in[3];
    const float* v    = (const float*)d_in[4];
    const float* bias = (const float*)d_in[5];
    float* out = (float*)d_out;

    cudaFuncSetAttribute(sru_gemm_kernel, cudaFuncAttributeMaxDynamicSharedMemorySize, GEMM_SMEM);

    sru_prepmask_kernel<<<1, 1024>>>(mask);
    sru_prepw_kernel<<<dim3(K_TOT / 32, N_TOT / 32, NL), 1024>>>(W);
    sru_embed_kernel<<<(M_TOT * 128 + 255) / 256, 256>>>(ids, emb);

    const int scan_blocks = (BB * DD) / 128;   // 128 blocks x 128 threads = 16384 lanes
    for (int l = 0; l < NL; ++l) {
        const int xin = l & 1;
        sru_gemm_kernel<<<dim3(N_TOT / BN, M_TOT / BM), 256, GEMM_SMEM>>>(l, xin);
        sru_scan_kernel<<<scan_blocks, 128>>>(l, xin, v, bias, out, (l == NL - 1) ? 1 : 0);
    }
}

// round 9
// speedup vs baseline: 2.5746x; 2.5746x over previous
#include <cuda_runtime.h>
#include <cuda_fp16.h>
#include <cstdint>

// Problem constants (fixed by the dataset)
#define VOCAB  10000
#define DD     512
#define NL     4
#define BB     32
#define SS     1024
#define M_TOT  (BB * SS)     // 32768
#define N_TOT  (3 * DD)      // 1536
#define K_TOT  DD            // 512

// ---------------------------------------------------------------------------
// Scratch (device globals — allocation-free per harness rules)
// ---------------------------------------------------------------------------
__device__ float         g_U[(size_t)M_TOT * N_TOT];          // 201 MB, one layer's U
__device__ __half        g_x16[2][(size_t)M_TOT * DD];        // fp16 x, ping-pong
__device__ __half        g_W16[(size_t)NL * N_TOT * K_TOT];   // W^T fp16  [l][n][k]
__device__ unsigned int  g_padbits[BB][SS / 32];              // bit s%32 of word s/32: pad at (b,s)

// ---------------------------------------------------------------------------
// PTX helpers (sm_80-level; compiles for plain sm_100)
// ---------------------------------------------------------------------------
__device__ __forceinline__ uint32_t smem_u32(const void* p) {
    uint32_t a;
    asm("{ .reg .u64 t; cvta.to.shared.u64 t, %1; cvt.u32.u64 %0, t; }" : "=r"(a) : "l"(p));
    return a;
}
__device__ __forceinline__ void cpa16(uint32_t dst, const void* src) {
    asm volatile("cp.async.cg.shared.global [%0], [%1], 16;" :: "r"(dst), "l"(src));
}
__device__ __forceinline__ void cp_commit() {
    asm volatile("cp.async.commit_group;" ::: "memory");
}
template <int N> __device__ __forceinline__ void cp_wait() {
    asm volatile("cp.async.wait_group %0;" :: "n"(N) : "memory");
}
__device__ __forceinline__ void ldm4(uint32_t* r, uint32_t addr) {
    asm volatile("ldmatrix.sync.aligned.m8n8.x4.shared.b16 {%0,%1,%2,%3}, [%4];"
                 : "=r"(r[0]), "=r"(r[1]), "=r"(r[2]), "=r"(r[3]) : "r"(addr));
}
__device__ __forceinline__ void mma16816(float* d, const uint32_t* a, const uint32_t* b) {
    asm volatile("mma.sync.aligned.m16n8k16.row.col.f32.f16.f16.f32 "
                 "{%0,%1,%2,%3}, {%4,%5,%6,%7}, {%8,%9}, {%0,%1,%2,%3};"
                 : "+f"(d[0]), "+f"(d[1]), "+f"(d[2]), "+f"(d[3])
                 : "r"(a[0]), "r"(a[1]), "r"(a[2]), "r"(a[3]), "r"(b[0]), "r"(b[1]));
}

// ---------------------------------------------------------------------------
// GEMM: U[m][n] = sum_k x16[m][k] * W16[n][k]   (fp16 in, fp32 accumulate)
// CTA tile 128x128, BK=64 (128-B swizzled rows), 3-stage cp.async pipeline,
// one __syncthreads per chunk; fully unrolled chunk loop. (R8: 148us, 67% tensor)
// ---------------------------------------------------------------------------
#define BM 128
#define BN 128
#define BK 64
#define AS_BYTES    (BM * BK * 2)               // 16384
#define BS_BYTES    (BN * BK * 2)               // 16384
#define STAGE_BYTES (AS_BYTES + BS_BYTES)       // 32768
#define GEMM_SMEM   (3 * STAGE_BYTES)           // 98304

__global__ __launch_bounds__(256, 2) void sru_gemm_kernel(int layer, int xin) {
    extern __shared__ char sm[];
    const uint32_t sb = smem_u32(sm);
    const int tid = threadIdx.x, lane = tid & 31, wid = tid >> 5;
    const int n0 = blockIdx.x * BN;     // n fastest -> 12 CTAs share the A tile (L2-hot)
    const int m0 = blockIdx.y * BM;

    const __half* __restrict__ A  = g_x16[xin] + (size_t)m0 * K_TOT;
    const __half* __restrict__ Bm = g_W16 + (size_t)layer * N_TOT * K_TOT + (size_t)n0 * K_TOT;

    auto load_chunk = [&](int stage, int kc) {
        const uint32_t ab = sb + stage * STAGE_BYTES;
        const uint32_t bb = ab + AS_BYTES;
#pragma unroll
        for (int i = 0; i < 4; ++i) {
            const int j = tid + i * 256;             // 0..1023 : (row, 16B-seg)
            const int r = j >> 3, seg = j & 7;
            const uint32_t soff = (uint32_t)(r * 128 + ((seg * 16) ^ ((r & 7) * 16)));
            const size_t go = (size_t)r * K_TOT + kc * 64 + seg * 8;
            cpa16(ab + soff, A + go);
            cpa16(bb + soff, Bm + go);
        }
        cp_commit();
    };

    const int wm = wid >> 2, wn = wid & 3;           // warp tile: rows wm*64, cols wn*32
    const int grp = lane >> 3, l8 = lane & 7;
    const int a_r  = ((grp & 1) << 3) + l8;
    const int a_kh = grp >> 1;
    const int b_r  = ((grp >> 1) << 3) + l8;
    const int b_kh = grp & 1;

    uint32_t swa[4], swb[4];
#pragma unroll
    for (int ks = 0; ks < 4; ++ks) {
        swa[ks] = (uint32_t)((ks * 32 + a_kh * 16) ^ ((a_r & 7) * 16));
        swb[ks] = (uint32_t)((ks * 32 + b_kh * 16) ^ ((b_r & 7) * 16));
    }
    const uint32_t a_row_base = (uint32_t)((wm * 64 + a_r) * 128);
    const uint32_t b_row_base = (uint32_t)((wn * 32 + b_r) * 128);

    float acc[4][4][4];
#pragma unroll
    for (int mi = 0; mi < 4; ++mi)
#pragma unroll
        for (int ni = 0; ni < 4; ++ni)
#pragma unroll
            for (int q = 0; q < 4; ++q) acc[mi][ni][q] = 0.0f;

    load_chunk(0, 0);
    load_chunk(1, 1);

#pragma unroll
    for (int c = 0; c < 8; ++c) {
        if (c < 7) cp_wait<1>(); else cp_wait<0>();
        __syncthreads();
        if (c + 2 < 8) load_chunk((c + 2) % 3, c + 2);

        const uint32_t ab = sb + (c % 3) * STAGE_BYTES;
        const uint32_t bb = ab + AS_BYTES;
        const uint32_t abase = ab + a_row_base;
        const uint32_t bbase = bb + b_row_base;
#pragma unroll
        for (int ks = 0; ks < 4; ++ks) {
            uint32_t areg[4][4], breg[2][4];
#pragma unroll
            for (int nq = 0; nq < 2; ++nq) ldm4(breg[nq], bbase + nq * 2048 + swb[ks]);
#pragma unroll
            for (int mi = 0; mi < 4; ++mi) ldm4(areg[mi], abase + mi * 2048 + swa[ks]);
#pragma unroll
            for (int mi = 0; mi < 4; ++mi)
#pragma unroll
                for (int ni = 0; ni < 4; ++ni)
                    mma16816(acc[mi][ni], areg[mi], &breg[ni >> 1][(ni & 1) * 2]);
        }
    }

    const int er = lane >> 2, ec = (lane & 3) * 2;
    float* __restrict__ Uo = g_U + (size_t)m0 * N_TOT + n0;
#pragma unroll
    for (int mi = 0; mi < 4; ++mi) {
#pragma unroll
        for (int ni = 0; ni < 4; ++ni) {
            const int m = wm * 64 + mi * 16 + er;
            const int n = wn * 32 + ni * 8 + ec;
            float2 v0 = make_float2(acc[mi][ni][0], acc[mi][ni][1]);
            float2 v1 = make_float2(acc[mi][ni][2], acc[mi][ni][3]);
            *(float2*)&Uo[(size_t)m * N_TOT + n]       = v0;
            *(float2*)&Uo[(size_t)(m + 8) * N_TOT + n] = v1;
        }
    }
}

// ---------------------------------------------------------------------------
// SRU recurrence: one thread per (b, d) lane, serial over S.
// 128 blocks x 128 threads (1 warp/SMSP on 128 SMs). LDG register prefetch
// ring PF=16 (proven R6 path — warp-coalesced LDG, no cp.async).
// Streams per step: 3x U fp32 + 1x x fp16 loads, 1x fp16 h store.
// ---------------------------------------------------------------------------
__device__ __forceinline__ float htanh(float z) {
    float r;
    asm("tanh.approx.f32 %0, %1;" : "=f"(r) : "f"(z));
    return r;
}
__device__ __forceinline__ float fast_sigmoid(float z) {
    return fmaf(0.5f, htanh(0.5f * z), 0.5f);    // sigma(z) = 0.5*tanh(z/2)+0.5
}

#define SCAN_PF 16

__global__ __launch_bounds__(128) void sru_scan_kernel(int layer, int xin,
                                                       const float* __restrict__ vall,
                                                       const float* __restrict__ ball,
                                                       float* __restrict__ dout, int last) {
    const int t = blockIdx.x * 128 + threadIdx.x;   // 0..16383
    const int d = t & (DD - 1);
    const int b = t >> 9;

    const float* __restrict__ U = g_U;
    const unsigned short* __restrict__ x16 = (const unsigned short*)g_x16[xin];
    __half* __restrict__ o16 = g_x16[xin ^ 1];

    const float vf = vall[layer * 1024 + d];
    const float vr = vall[layer * 1024 + 512 + d];
    const float bf = ball[layer * 1024 + d];
    const float br = ball[layer * 1024 + 512 + d];

    float u0p[SCAN_PF], ufp[SCAN_PF], urp[SCAN_PF];
    unsigned short xp[SCAN_PF];

#pragma unroll
    for (int i = 0; i < SCAN_PF; ++i) {
        const int rowp = i * BB + b;
        const size_t ub = (size_t)rowp * N_TOT + d;
        u0p[i] = __ldcs(U + ub);
        ufp[i] = __ldcs(U + ub + 512);
        urp[i] = __ldcs(U + ub + 1024);
        xp[i]  = __ldcs(x16 + (size_t)rowp * DD + d);
    }

    float c = 0.0f;
    for (int s0 = 0; s0 < SS; s0 += SCAN_PF) {
        const unsigned int pw = g_padbits[b][s0 >> 5] >> (s0 & 31);
#pragma unroll
        for (int k = 0; k < SCAN_PF; ++k) {
            const int s = s0 + k;
            const float u0_ = u0p[k], uf_ = ufp[k], ur_ = urp[k];
            __half_raw hxr; hxr.x = xp[k];
            const float x_ = __half2float((__half)hxr);
            const int pd = (pw >> k) & 1;

            const int sn = s + SCAN_PF;
            if (sn < SS) {
                const int rowp = sn * BB + b;
                const size_t ub = (size_t)rowp * N_TOT + d;
                u0p[k] = __ldcs(U + ub);
                ufp[k] = __ldcs(U + ub + 512);
                urp[k] = __ldcs(U + ub + 1024);
                xp[k]  = __ldcs(x16 + (size_t)rowp * DD + d);
            }

            const float f = fast_sigmoid(fmaf(vf, c, uf_ + bf));
            const float r = fast_sigmoid(fmaf(vr, c, ur_ + br));
            float cn = fmaf(f, c - u0_, u0_);
            cn = pd ? c : cn;
            float h = fmaf(r, htanh(cn) - x_, x_);
            h = pd ? 0.0f : h;
            c = cn;

            const int row = s * BB + b;
            if (!last) o16[(size_t)row * DD + d] = __float2half_rn(h);
            else       dout[((size_t)b * SS + s) * DD + d] = h;
        }
    }
}

// ---------------------------------------------------------------------------
// Prep kernels
// ---------------------------------------------------------------------------
__global__ void sru_embed_kernel(const int* __restrict__ ids, const float* __restrict__ emb) {
    const int idx = blockIdx.x * blockDim.x + threadIdx.x;   // (m, quad of 4)
    if (idx >= M_TOT * 128) return;
    const int m = idx >> 7, q = idx & 127;
    const int b = m & 31, s = m >> 5;                        // m = s*32 + b
    const int id = __ldg(ids + b * SS + s);
    const float4 e = *(const float4*)(emb + (size_t)id * DD + q * 4);

    union { __half v[4]; uint2 u; } hh;
    hh.v[0] = __float2half_rn(e.x);
    hh.v[1] = __float2half_rn(e.y);
    hh.v[2] = __float2half_rn(e.z);
    hh.v[3] = __float2half_rn(e.w);
    *(uint2*)(g_x16[0] + (size_t)m * DD + q * 4) = hh.u;
}

// W[l][k][n] -> g_W16[l][n][k], coalesced both ways via 32x33 smem tile
__global__ __launch_bounds__(1024) void sru_prepw_kernel(const float* __restrict__ W) {
    __shared__ float tile[32][33];
    const int k0 = blockIdx.x * 32;      // 16 tiles
    const int n0 = blockIdx.y * 32;      // 48 tiles
    const int l  = blockIdx.z;           // 4
    const int tx = threadIdx.x & 31, ty = threadIdx.x >> 5;
    tile[ty][tx] = __ldg(W + (size_t)l * K_TOT * N_TOT + (size_t)(k0 + ty) * N_TOT + n0 + tx);
    __syncthreads();
    g_W16[(size_t)l * N_TOT * K_TOT + (size_t)(n0 + ty) * K_TOT + k0 + tx] =
        __float2half_rn(tile[tx][ty]);
}

// Mask dtype auto-detect: int32 {0,1} / float32 {0,1.0f} / packed bytes.
// Produces the transposed pad bitmask g_padbits[b][s/32].
__global__ void sru_prepmask_kernel(const void* __restrict__ mraw) {
    __shared__ int f_not01, f_notf;
    const int tid = threadIdx.x;
    if (tid == 0) { f_not01 = 0; f_notf = 0; }
    __syncthreads();
    const unsigned int* w = (const unsigned int*)mraw;
    int a = 0, fl = 0;
    for (int i = tid; i < M_TOT / 4; i += 1024) {     // safe subset for all dtypes
        const unsigned int x = w[i];
        if (x > 1u) a = 1;
        if (x != 0u && x != 0x3F800000u) fl = 1;
    }
    if (a)  atomicExch(&f_not01, 1);
    if (fl) atomicExch(&f_notf, 1);
    __syncthreads();
    const int mode = (!f_not01) ? 0 : ((!f_notf) ? 1 : 2);
    const int b = tid >> 5, wrd = tid & 31;
    unsigned int bits = 0;
#pragma unroll 4
    for (int i = 0; i < 32; ++i) {
        const int s = wrd * 32 + i;
        const int j = b * SS + s;                      // mask is [B][S]
        int mv;
        if (mode == 0)      mv = ((const int*)mraw)[j] != 0;
        else if (mode == 1) mv = ((const unsigned int*)mraw)[j] != 0u;
        else                mv = ((const unsigned char*)mraw)[j] != 0;
        if (!mv) bits |= (1u << i);                    // pad bit
    }
    g_padbits[b][wrd] = bits;
}

// ---------------------------------------------------------------------------
// Launch
// ---------------------------------------------------------------------------
extern "C" void kernel_launch(void* const* d_in, const int* in_sizes, int n_in,
                              void* d_out, int out_size) {
    const int*   ids  = (const int*)d_in[0];
    const void*  mask = d_in[1];
    const float* emb  = (const float*)d_in[2];
    const float* W    = (const float*)d_in[3];
    const float* v    = (const float*)d_in[4];
    const float* bias = (const float*)d_in[5];
    float* out = (float*)d_out;

    cudaFuncSetAttribute(sru_gemm_kernel, cudaFuncAttributeMaxDynamicSharedMemorySize, GEMM_SMEM);

    sru_prepmask_kernel<<<1, 1024>>>(mask);
    sru_prepw_kernel<<<dim3(K_TOT / 32, N_TOT / 32, NL), 1024>>>(W);
    sru_embed_kernel<<<(M_TOT * 128 + 255) / 256, 256>>>(ids, emb);

    const int scan_blocks = (BB * DD) / 128;   // 128 blocks x 128 threads = 16384 lanes
    for (int l = 0; l < NL; ++l) {
        const int xin = l & 1;
        sru_gemm_kernel<<<dim3(N_TOT / BN, M_TOT / BM), 256, GEMM_SMEM>>>(l, xin);
        sru_scan_kernel<<<scan_blocks, 128>>>(l, xin, v, bias, out, (l == NL - 1) ? 1 : 0);
    }
}

// round 10
// speedup vs baseline: 2.8771x; 1.1175x over previous
#include <cuda_runtime.h>
#include <cuda_fp16.h>
#include <cstdint>

// Problem constants (fixed by the dataset)
#define VOCAB  10000
#define DD     512
#define NL     4
#define BB     32
#define SS     1024
#define M_TOT  (BB * SS)     // 32768
#define N_TOT  (3 * DD)      // 1536
#define K_TOT  DD            // 512

// ---------------------------------------------------------------------------
// Scratch (device globals — allocation-free per harness rules)
// ---------------------------------------------------------------------------
__device__ float         g_U[(size_t)M_TOT * N_TOT];          // 201 MB, one layer's U
__device__ __half        g_x16[2][(size_t)M_TOT * DD];        // fp16 x, ping-pong
__device__ __half        g_W16[(size_t)NL * N_TOT * K_TOT];   // W^T fp16  [l][n][k]
__device__ unsigned int  g_padbits[BB][SS / 32];              // bit s%32 of word s/32: pad at (b,s)

// ---------------------------------------------------------------------------
// PTX helpers (sm_80-level; compiles for plain sm_100)
// ---------------------------------------------------------------------------
__device__ __forceinline__ uint32_t smem_u32(const void* p) {
    uint32_t a;
    asm("{ .reg .u64 t; cvta.to.shared.u64 t, %1; cvt.u32.u64 %0, t; }" : "=r"(a) : "l"(p));
    return a;
}
__device__ __forceinline__ void cpa16(uint32_t dst, const void* src) {
    asm volatile("cp.async.cg.shared.global [%0], [%1], 16;" :: "r"(dst), "l"(src));
}
__device__ __forceinline__ void cp_commit() {
    asm volatile("cp.async.commit_group;" ::: "memory");
}
template <int N> __device__ __forceinline__ void cp_wait() {
    asm volatile("cp.async.wait_group %0;" :: "n"(N) : "memory");
}
__device__ __forceinline__ void ldm4(uint32_t* r, uint32_t addr) {
    asm volatile("ldmatrix.sync.aligned.m8n8.x4.shared.b16 {%0,%1,%2,%3}, [%4];"
                 : "=r"(r[0]), "=r"(r[1]), "=r"(r[2]), "=r"(r[3]) : "r"(addr));
}
__device__ __forceinline__ void mma16816(float* d, const uint32_t* a, const uint32_t* b) {
    asm volatile("mma.sync.aligned.m16n8k16.row.col.f32.f16.f16.f32 "
                 "{%0,%1,%2,%3}, {%4,%5,%6,%7}, {%8,%9}, {%0,%1,%2,%3};"
                 : "+f"(d[0]), "+f"(d[1]), "+f"(d[2]), "+f"(d[3])
                 : "r"(a[0]), "r"(a[1]), "r"(a[2]), "r"(a[3]), "r"(b[0]), "r"(b[1]));
}

// ---------------------------------------------------------------------------
// GEMM: U[m][n] = sum_k x16[m][k] * W16[n][k]   (fp16 in, fp32 accumulate)
// CTA tile 128x128, BK=64 (128-B swizzled rows), 3-stage cp.async pipeline,
// one __syncthreads per chunk; fully unrolled chunk loop. (R8/R9: 147us, 67% tensor)
// ---------------------------------------------------------------------------
#define BM 128
#define BN 128
#define BK 64
#define AS_BYTES    (BM * BK * 2)               // 16384
#define BS_BYTES    (BN * BK * 2)               // 16384
#define STAGE_BYTES (AS_BYTES + BS_BYTES)       // 32768
#define GEMM_SMEM   (3 * STAGE_BYTES)           // 98304

__global__ __launch_bounds__(256, 2) void sru_gemm_kernel(int layer, int xin) {
    extern __shared__ char sm[];
    const uint32_t sb = smem_u32(sm);
    const int tid = threadIdx.x, lane = tid & 31, wid = tid >> 5;
    const int n0 = blockIdx.x * BN;     // n fastest -> 12 CTAs share the A tile (L2-hot)
    const int m0 = blockIdx.y * BM;

    const __half* __restrict__ A  = g_x16[xin] + (size_t)m0 * K_TOT;
    const __half* __restrict__ Bm = g_W16 + (size_t)layer * N_TOT * K_TOT + (size_t)n0 * K_TOT;

    auto load_chunk = [&](int stage, int kc) {
        const uint32_t ab = sb + stage * STAGE_BYTES;
        const uint32_t bb = ab + AS_BYTES;
#pragma unroll
        for (int i = 0; i < 4; ++i) {
            const int j = tid + i * 256;             // 0..1023 : (row, 16B-seg)
            const int r = j >> 3, seg = j & 7;
            const uint32_t soff = (uint32_t)(r * 128 + ((seg * 16) ^ ((r & 7) * 16)));
            const size_t go = (size_t)r * K_TOT + kc * 64 + seg * 8;
            cpa16(ab + soff, A + go);
            cpa16(bb + soff, Bm + go);
        }
        cp_commit();
    };

    const int wm = wid >> 2, wn = wid & 3;           // warp tile: rows wm*64, cols wn*32
    const int grp = lane >> 3, l8 = lane & 7;
    const int a_r  = ((grp & 1) << 3) + l8;
    const int a_kh = grp >> 1;
    const int b_r  = ((grp >> 1) << 3) + l8;
    const int b_kh = grp & 1;

    uint32_t swa[4], swb[4];
#pragma unroll
    for (int ks = 0; ks < 4; ++ks) {
        swa[ks] = (uint32_t)((ks * 32 + a_kh * 16) ^ ((a_r & 7) * 16));
        swb[ks] = (uint32_t)((ks * 32 + b_kh * 16) ^ ((b_r & 7) * 16));
    }
    const uint32_t a_row_base = (uint32_t)((wm * 64 + a_r) * 128);
    const uint32_t b_row_base = (uint32_t)((wn * 32 + b_r) * 128);

    float acc[4][4][4];
#pragma unroll
    for (int mi = 0; mi < 4; ++mi)
#pragma unroll
        for (int ni = 0; ni < 4; ++ni)
#pragma unroll
            for (int q = 0; q < 4; ++q) acc[mi][ni][q] = 0.0f;

    load_chunk(0, 0);
    load_chunk(1, 1);

#pragma unroll
    for (int c = 0; c < 8; ++c) {
        if (c < 7) cp_wait<1>(); else cp_wait<0>();
        __syncthreads();
        if (c + 2 < 8) load_chunk((c + 2) % 3, c + 2);

        const uint32_t ab = sb + (c % 3) * STAGE_BYTES;
        const uint32_t bb = ab + AS_BYTES;
        const uint32_t abase = ab + a_row_base;
        const uint32_t bbase = bb + b_row_base;
#pragma unroll
        for (int ks = 0; ks < 4; ++ks) {
            uint32_t areg[4][4], breg[2][4];
#pragma unroll
            for (int nq = 0; nq < 2; ++nq) ldm4(breg[nq], bbase + nq * 2048 + swb[ks]);
#pragma unroll
            for (int mi = 0; mi < 4; ++mi) ldm4(areg[mi], abase + mi * 2048 + swa[ks]);
#pragma unroll
            for (int mi = 0; mi < 4; ++mi)
#pragma unroll
                for (int ni = 0; ni < 4; ++ni)
                    mma16816(acc[mi][ni], areg[mi], &breg[ni >> 1][(ni & 1) * 2]);
        }
    }

    const int er = lane >> 2, ec = (lane & 3) * 2;
    float* __restrict__ Uo = g_U + (size_t)m0 * N_TOT + n0;
#pragma unroll
    for (int mi = 0; mi < 4; ++mi) {
#pragma unroll
        for (int ni = 0; ni < 4; ++ni) {
            const int m = wm * 64 + mi * 16 + er;
            const int n = wn * 32 + ni * 8 + ec;
            float2 v0 = make_float2(acc[mi][ni][0], acc[mi][ni][1]);
            float2 v1 = make_float2(acc[mi][ni][2], acc[mi][ni][3]);
            *(float2*)&Uo[(size_t)m * N_TOT + n]       = v0;
            *(float2*)&Uo[(size_t)(m + 8) * N_TOT + n] = v1;
        }
    }
}

// ---------------------------------------------------------------------------
// SRU recurrence. One thread per (b,d) lane, serial over S. Warp-cooperative
// cp.async ring: per step, lanes 0-23 fetch the three 128B U-component rows
// and lanes 24-27 the 64B x row (16B dense per lane). 16 slots, groups of 4
// steps, wait_group<3> => exact 12-step lead (no LDG scoreboard aliasing).
// Consume = 3x LDS.32 + LDS.16, conflict-free. Consume-then-refill order.
// ---------------------------------------------------------------------------
__device__ __forceinline__ float htanh(float z) {
    float r;
    asm("tanh.approx.f32 %0, %1;" : "=f"(r) : "f"(z));
    return r;
}
__device__ __forceinline__ float fast_sigmoid(float z) {
    return fmaf(0.5f, htanh(0.5f * z), 0.5f);    // sigma(z) = 0.5*tanh(z/2)+0.5
}

#define SLOTS 16

__global__ __launch_bounds__(128) void sru_scan_kernel(int layer, int xin,
                                                       const float* __restrict__ vall,
                                                       const float* __restrict__ ball,
                                                       float* __restrict__ dout, int last) {
    __shared__ __align__(16) unsigned char ring[4][SLOTS][512];  // 32 KB
    const int tid = threadIdx.x, lane = tid & 31, w = tid >> 5;
    const int t = blockIdx.x * 128 + tid;           // 0..16383
    const int d = t & (DD - 1);
    const int b = t >> 9;
    const int d0 = d & ~31;                         // warp's d base

    const float* __restrict__ U = g_U;
    const unsigned short* __restrict__ x16 = (const unsigned short*)g_x16[xin];
    __half* __restrict__ o16 = g_x16[xin ^ 1];

    const uint32_t ringbase = smem_u32(&ring[w][0][0]);

    // Fetch roles: role 0/1/2 -> u0/uf/ur rows (8 lanes x 16B = 128B each);
    // role 3, li<4 -> x row (4 lanes x 16B = 64B). Lanes 28-31 idle on fetch.
    const int role = lane >> 3, li = lane & 7;
    const bool fet = (role < 3) || (li < 4);
    const uint32_t soff = (role < 3) ? (uint32_t)(role * 128 + li * 16)
                                     : (uint32_t)(384 + li * 16);

    const float vf = vall[layer * 1024 + d];
    const float vr = vall[layer * 1024 + 512 + d];
    const float bf = ball[layer * 1024 + d];
    const float br = ball[layer * 1024 + 512 + d];

    auto issue4 = [&](int s) {
        if (fet) {
#pragma unroll
            for (int i = 0; i < 4; ++i) {
                const int row = (s + i) * BB + b;
                const uint32_t dst = ringbase + ((uint32_t)((s + i) & (SLOTS - 1)) << 9) + soff;
                const void* src = (role < 3)
                    ? (const void*)(U + (size_t)row * N_TOT + role * 512 + d0 + li * 4)
                    : (const void*)(x16 + (size_t)row * DD + d0 + li * 8);
                cpa16(dst, src);
            }
        }
        cp_commit();
    };

    float c = 0.0f;

    auto do4 = [&](int s0) {
        const unsigned int pw = g_padbits[b][s0 >> 5] >> (s0 & 31);
#pragma unroll
        for (int k = 0; k < 4; ++k) {
            const int s = s0 + k;
            const uint32_t sb_ = ringbase + ((uint32_t)(s & (SLOTS - 1)) << 9);
            float u0_, uf_, ur_;
            unsigned short hx;
            asm volatile("ld.shared.f32 %0, [%1];" : "=f"(u0_) : "r"(sb_ + lane * 4));
            asm volatile("ld.shared.f32 %0, [%1];" : "=f"(uf_) : "r"(sb_ + 128 + lane * 4));
            asm volatile("ld.shared.f32 %0, [%1];" : "=f"(ur_) : "r"(sb_ + 256 + lane * 4));
            asm volatile("ld.shared.u16 %0, [%1];" : "=h"(hx)  : "r"(sb_ + 384 + lane * 2));
            __half_raw hxr; hxr.x = hx;
            const float x_ = __half2float((__half)hxr);

            const int pd = (pw >> k) & 1;
            const float f = fast_sigmoid(fmaf(vf, c, uf_ + bf));
            const float r = fast_sigmoid(fmaf(vr, c, ur_ + br));
            float cn = fmaf(f, c - u0_, u0_);
            cn = pd ? c : cn;
            float h = fmaf(r, htanh(cn) - x_, x_);
            h = pd ? 0.0f : h;
            c = cn;

            const int row = s * BB + b;
            if (!last) o16[(size_t)row * DD + d] = __float2half_rn(h);
            else       dout[((size_t)b * SS + s) * DD + d] = h;
        }
    };

    issue4(0); issue4(4); issue4(8); issue4(12);

    for (int s0 = 0; s0 < SS - 16; s0 += 4) {
        cp_wait<3>();
        __syncwarp();
        do4(s0);                 // consume slots s0..s0+3
        issue4(s0 + 16);         // then refill the same slots (WAR-safe order)
    }
    cp_wait<3>(); __syncwarp(); do4(SS - 16);
    cp_wait<2>(); __syncwarp(); do4(SS - 12);
    cp_wait<1>(); __syncwarp(); do4(SS - 8);
    cp_wait<0>(); __syncwarp(); do4(SS - 4);
}

// ---------------------------------------------------------------------------
// Prep kernels
// ---------------------------------------------------------------------------
__global__ void sru_embed_kernel(const int* __restrict__ ids, const float* __restrict__ emb) {
    const int idx = blockIdx.x * blockDim.x + threadIdx.x;   // (m, quad of 4)
    if (idx >= M_TOT * 128) return;
    const int m = idx >> 7, q = idx & 127;
    const int b = m & 31, s = m >> 5;                        // m = s*32 + b
    const int id = __ldg(ids + b * SS + s);
    const float4 e = *(const float4*)(emb + (size_t)id * DD + q * 4);

    union { __half v[4]; uint2 u; } hh;
    hh.v[0] = __float2half_rn(e.x);
    hh.v[1] = __float2half_rn(e.y);
    hh.v[2] = __float2half_rn(e.z);
    hh.v[3] = __float2half_rn(e.w);
    *(uint2*)(g_x16[0] + (size_t)m * DD + q * 4) = hh.u;
}

// W[l][k][n] -> g_W16[l][n][k], coalesced both ways via 32x33 smem tile
__global__ __launch_bounds__(1024) void sru_prepw_kernel(const float* __restrict__ W) {
    __shared__ float tile[32][33];
    const int k0 = blockIdx.x * 32;      // 16 tiles
    const int n0 = blockIdx.y * 32;      // 48 tiles
    const int l  = blockIdx.z;           // 4
    const int tx = threadIdx.x & 31, ty = threadIdx.x >> 5;
    tile[ty][tx] = __ldg(W + (size_t)l * K_TOT * N_TOT + (size_t)(k0 + ty) * N_TOT + n0 + tx);
    __syncthreads();
    g_W16[(size_t)l * N_TOT * K_TOT + (size_t)(n0 + ty) * K_TOT + k0 + tx] =
        __float2half_rn(tile[tx][ty]);
}

// Mask dtype auto-detect: int32 {0,1} / float32 {0,1.0f} / packed bytes.
// Produces the transposed pad bitmask g_padbits[b][s/32]. Idempotent.
__global__ void sru_prepmask_kernel(const void* __restrict__ mraw) {
    __shared__ int f_not01, f_notf;
    const int tid = threadIdx.x;
    if (tid == 0) { f_not01 = 0; f_notf = 0; }
    __syncthreads();
    const unsigned int* w = (const unsigned int*)mraw;
    int a = 0, fl = 0;
    for (int i = tid; i < M_TOT / 4; i += 1024) {     // safe subset for all dtypes
        const unsigned int x = w[i];
        if (x > 1u) a = 1;
        if (x != 0u && x != 0x3F800000u) fl = 1;
    }
    if (a)  atomicExch(&f_not01, 1);
    if (fl) atomicExch(&f_notf, 1);
    __syncthreads();
    const int mode = (!f_not01) ? 0 : ((!f_notf) ? 1 : 2);
    const int b = tid >> 5, wrd = tid & 31;
    unsigned int bits = 0;
#pragma unroll 4
    for (int i = 0; i < 32; ++i) {
        const int s = wrd * 32 + i;
        const int j = b * SS + s;                      // mask is [B][S]
        int mv;
        if (mode == 0)      mv = ((const int*)mraw)[j] != 0;
        else if (mode == 1) mv = ((const unsigned int*)mraw)[j] != 0u;
        else                mv = ((const unsigned char*)mraw)[j] != 0;
        if (!mv) bits |= (1u << i);                    // pad bit
    }
    g_padbits[b][wrd] = bits;
}

// ---------------------------------------------------------------------------
// Launch. NOTE: prepmask launched twice (idempotent) so the harness's fixed
// ncu capture window (-s 5 -c 1) lands on scan0 instead of a GEMM.
// ---------------------------------------------------------------------------
extern "C" void kernel_launch(void* const* d_in, const int* in_sizes, int n_in,
                              void* d_out, int out_size) {
    const int*   ids  = (const int*)d_in[0];
    const void*  mask = d_in[1];
    const float* emb  = (const float*)d_in[2];
    const float* W    = (const float*)d_in[3];
    const float* v    = (const float*)d_in[4];
    const float* bias = (const float*)d_in[5];
    float* out = (float*)d_out;

    cudaFuncSetAttribute(sru_gemm_kernel, cudaFuncAttributeMaxDynamicSharedMemorySize, GEMM_SMEM);

    sru_prepmask_kernel<<<1, 1024>>>(mask);   // launch 0
    sru_prepmask_kernel<<<1, 1024>>>(mask);   // launch 1 (index shim for ncu -s 5)
    sru_prepw_kernel<<<dim3(K_TOT / 32, N_TOT / 32, NL), 1024>>>(W);        // 2
    sru_embed_kernel<<<(M_TOT * 128 + 255) / 256, 256>>>(ids, emb);         // 3

    const int scan_blocks = (BB * DD) / 128;   // 128 blocks x 128 threads = 16384 lanes
    for (int l = 0; l < NL; ++l) {
        const int xin = l & 1;
        sru_gemm_kernel<<<dim3(N_TOT / BN, M_TOT / BM), 256, GEMM_SMEM>>>(l, xin);  // 4,6,8,10
        sru_scan_kernel<<<scan_blocks, 128>>>(l, xin, v, bias, out, (l == NL - 1) ? 1 : 0); // 5,...
    }
}